// round 3
// baseline (speedup 1.0000x reference)
#include <cuda_runtime.h>
#include <cuda_fp16.h>
#include <cstdint>

// ============================================================================
// Problem constants
// ============================================================================
static constexpr int M_TOT = 8192;   // B*S
static constexpr int N_TOT = 4096;   // out_features
static constexpr int K_TOT = 4096;   // in_features
static constexpr int GROUP = 128;
static constexpr int NPROF = 8;
static constexpr int GTOT  = N_TOT * K_TOT / GROUP;

// GEMM tiling: CTA 256x128x64, warp tile 64x64 (8 warps: 4M x 2N)
static constexpr int BM = 256;
static constexpr int BN = 128;
static constexpr int BK = 64;                 // fp16 elems -> 128B rows
static constexpr int KITERS = K_TOT / BK;     // 64
static constexpr int STAGES = 4;

static constexpr int A_BYTES = BM * 128;      // 32768
static constexpr int B_BYTES = BN * 128;      // 16384
static constexpr int STAGE_BYTES = A_BYTES + B_BYTES;      // 49152
static constexpr int SMEM_TOTAL  = STAGES * STAGE_BYTES;   // 196608

static constexpr int THREADS = 256;           // 8 warps

// ============================================================================
// Scratch device globals (no runtime allocation allowed)
// ============================================================================
__device__ __align__(1024) __half g_A[(size_t)M_TOT * K_TOT];  // 64 MB fp16 x
__device__ __align__(1024) __half g_B[(size_t)N_TOT * K_TOT];  // 32 MB fp16 W

// ============================================================================
// PTX helpers (baseline features only — harness assembles at plain sm_103)
// ============================================================================
__device__ __forceinline__ uint32_t smem_u32(const void* p) {
    uint32_t a;
    asm("{ .reg .u64 t; cvta.to.shared.u64 t, %1; cvt.u32.u64 %0, t; }" : "=r"(a) : "l"(p));
    return a;
}
__device__ __forceinline__ void cp_async16(uint32_t dst, const void* src) {
    asm volatile("cp.async.cg.shared.global [%0], [%1], 16;" :: "r"(dst), "l"(src) : "memory");
}
__device__ __forceinline__ void cp_commit() {
    asm volatile("cp.async.commit_group;" ::: "memory");
}
template <int N>
__device__ __forceinline__ void cp_wait() {
    asm volatile("cp.async.wait_group %0;" :: "n"(N) : "memory");
}
#define LDSM_X4(r0, r1, r2, r3, addr)                                              \
    asm volatile("ldmatrix.sync.aligned.m8n8.x4.shared.b16 {%0,%1,%2,%3}, [%4];"   \
                 : "=r"(r0), "=r"(r1), "=r"(r2), "=r"(r3) : "r"(addr))

__device__ __forceinline__ void mma16816(float* c, const uint32_t* a, uint32_t b0, uint32_t b1) {
    asm volatile(
        "mma.sync.aligned.m16n8k16.row.col.f32.f16.f16.f32 "
        "{%0,%1,%2,%3}, {%4,%5,%6,%7}, {%8,%9}, {%0,%1,%2,%3};"
        : "+f"(c[0]), "+f"(c[1]), "+f"(c[2]), "+f"(c[3])
        : "r"(a[0]), "r"(a[1]), "r"(a[2]), "r"(a[3]), "r"(b0), "r"(b1));
}

// ============================================================================
// Prep 1: x fp32 -> fp16 row-major [M, K]
// ============================================================================
__global__ void __launch_bounds__(256) prep_x_kernel(const float* __restrict__ x) {
    const int idx0 = blockIdx.x * 256 + threadIdx.x;
    const float4* __restrict__ x4 = (const float4*)x;
    uint2* __restrict__ dst = (uint2*)g_A;
#pragma unroll
    for (int i = 0; i < 4; i++) {
        const int id = idx0 + i * (M_TOT * K_TOT / 4 / 4);
        float4 v = x4[id];
        __half2 h0 = __floats2half2_rn(v.x, v.y);
        __half2 h1 = __floats2half2_rn(v.z, v.w);
        uint2 u;
        u.x = *reinterpret_cast<uint32_t*>(&h0);
        u.y = *reinterpret_cast<uint32_t*>(&h1);
        dst[id] = u;
    }
}

// ============================================================================
// Prep 2: W[n][k] = sign[n][k] * (routing . profile_scales)[n*32 + k/128], fp16
// ============================================================================
__global__ void __launch_bounds__(256) prep_w_kernel(const float* __restrict__ signs,
                                                     const float* __restrict__ ps,
                                                     const float* __restrict__ routing) {
    __shared__ float s_rt[NPROF];
    __shared__ float s_sc[K_TOT / GROUP];
    const int n = blockIdx.x;
    const int tid = threadIdx.x;
    if (tid < NPROF) s_rt[tid] = routing[tid];
    __syncthreads();
    if (tid < K_TOT / GROUP) {
        const int g = n * (K_TOT / GROUP) + tid;
        float s = 0.f;
#pragma unroll
        for (int p = 0; p < NPROF; p++) s += s_rt[p] * ps[(size_t)p * GTOT + g];
        s_sc[tid] = s;
    }
    __syncthreads();

    const float sc = s_sc[tid >> 3];
    const float4* __restrict__ sr = (const float4*)(signs + (size_t)n * K_TOT) + tid * 4;
    uint2* __restrict__ dst = (uint2*)(g_B + (size_t)n * K_TOT + tid * 16);
#pragma unroll
    for (int j = 0; j < 4; j++) {
        float4 v = sr[j];
        __half2 h0 = __floats2half2_rn(v.x * sc, v.y * sc);
        __half2 h1 = __floats2half2_rn(v.z * sc, v.w * sc);
        uint2 u;
        u.x = *reinterpret_cast<uint32_t*>(&h0);
        u.y = *reinterpret_cast<uint32_t*>(&h1);
        dst[j] = u;
    }
}

// ============================================================================
// GEMM: out[M,N] = Ah @ Bh^T, fp32 accum.  CTA 256x128x64, warp 64x64.
// ============================================================================
__global__ void __launch_bounds__(THREADS, 1) gemm_kernel(float* __restrict__ out) {
    extern __shared__ __align__(1024) unsigned char smem[];
    const uint32_t sb = smem_u32(smem);
    const int tid = threadIdx.x;
    const int wid = tid >> 5;
    const int lid = tid & 31;

    const int mBlk = blockIdx.x >> 5;       // 0..31
    const int nBlk = blockIdx.x & 31;       // 0..31
    const int mBase = mBlk * BM;
    const int nBase = nBlk * BN;

    const int wm = wid >> 1;                // 0..3
    const int wn = wid & 1;                 // 0..1
    const int wmBase = wm * 64;
    const int wnBase = wn * 64;

    // ---- per-lane ldmatrix address components ----
    // A: four m16 tiles per warp
    int rowOffA[4], xorA[4];
    const int hiA = (lid >> 4) & 1;
#pragma unroll
    for (int mi = 0; mi < 4; mi++) {
        int r = wmBase + mi * 16 + ((lid >> 3) & 1) * 8 + (lid & 7);
        rowOffA[mi] = r * 128;
        xorA[mi] = r & 7;
    }
    // B: four n16 groups (each covers two n8 tiles)
    int rowOffB[4], xorB[4];
    const int hiB = (lid >> 3) & 1;
#pragma unroll
    for (int g = 0; g < 4; g++) {
        int r = wnBase + g * 16 + ((lid >> 4) & 1) * 8 + (lid & 7);
        rowOffB[g] = r * 128;
        xorB[g] = r & 7;
    }

    float acc[4][8][4];
#pragma unroll
    for (int mi = 0; mi < 4; mi++)
#pragma unroll
        for (int ni = 0; ni < 8; ni++)
#pragma unroll
            for (int j = 0; j < 4; j++) acc[mi][ni][j] = 0.f;

    const __half* __restrict__ gApan = g_A + (size_t)mBase * K_TOT;
    const __half* __restrict__ gBpan = g_B + (size_t)nBase * K_TOT;

    // ---- stage loader: A 2048 + B 1024 16B chunks over 256 threads ----
    auto load_stage = [&](int kt, int st) {
        const uint32_t stA = sb + st * STAGE_BYTES;
        const uint32_t stB = stA + A_BYTES;
        const __half* srcA = gApan + kt * BK;
        const __half* srcB = gBpan + kt * BK;
#pragma unroll
        for (int i = 0; i < 8; i++) {           // A
            int t = tid + i * THREADS;
            int row = t >> 3, c16 = t & 7;
            uint32_t dst = stA + row * 128 + ((c16 ^ (row & 7)) << 4);
            cp_async16(dst, srcA + (size_t)row * K_TOT + c16 * 8);
        }
#pragma unroll
        for (int i = 0; i < 4; i++) {           // B
            int t = tid + i * THREADS;
            int row = t >> 3, c16 = t & 7;
            uint32_t dst = stB + row * 128 + ((c16 ^ (row & 7)) << 4);
            cp_async16(dst, srcB + (size_t)row * K_TOT + c16 * 8);
        }
        cp_commit();
    };

    // ---- prologue ----
#pragma unroll
    for (int s = 0; s < STAGES - 1; s++) load_stage(s, s);

    // ---- main loop ----
    for (int kt = 0; kt < KITERS; kt++) {
        cp_wait<STAGES - 2>();
        __syncthreads();

        if (kt + STAGES - 1 < KITERS) load_stage(kt + STAGES - 1, (kt + STAGES - 1) & (STAGES - 1));

        const int st = kt & (STAGES - 1);
        const uint32_t stA = sb + st * STAGE_BYTES;
        const uint32_t stB = stA + A_BYTES;

#pragma unroll
        for (int ks = 0; ks < 4; ks++) {
            uint32_t a[4][4];
#pragma unroll
            for (int mi = 0; mi < 4; mi++) {
                uint32_t addr = stA + rowOffA[mi] + (((ks * 2 + hiA) ^ xorA[mi]) << 4);
                LDSM_X4(a[mi][0], a[mi][1], a[mi][2], a[mi][3], addr);
            }
            uint32_t b[4][4];
#pragma unroll
            for (int g = 0; g < 4; g++) {
                uint32_t addr = stB + rowOffB[g] + (((ks * 2 + hiB) ^ xorB[g]) << 4);
                LDSM_X4(b[g][0], b[g][1], b[g][2], b[g][3], addr);
            }
#pragma unroll
            for (int mi = 0; mi < 4; mi++)
#pragma unroll
                for (int ni = 0; ni < 8; ni++) {
                    const int g = ni >> 1, sel = (ni & 1) * 2;
                    mma16816(acc[mi][ni], a[mi], b[g][sel], b[g][sel + 1]);
                }
        }
    }

    // ---- epilogue: direct fp32 stores ----
    const int gr = lid >> 2, tig = lid & 3;
#pragma unroll
    for (int mi = 0; mi < 4; mi++) {
        const int row0 = mBase + wmBase + mi * 16 + gr;
#pragma unroll
        for (int ni = 0; ni < 8; ni++) {
            const int col = nBase + wnBase + ni * 8 + tig * 2;
            float2* p0 = reinterpret_cast<float2*>(out + (size_t)row0 * N_TOT + col);
            float2* p1 = reinterpret_cast<float2*>(out + (size_t)(row0 + 8) * N_TOT + col);
            *p0 = make_float2(acc[mi][ni][0], acc[mi][ni][1]);
            *p1 = make_float2(acc[mi][ni][2], acc[mi][ni][3]);
        }
    }
}

// ============================================================================
// Launch
// ============================================================================
extern "C" void kernel_launch(void* const* d_in, const int* in_sizes, int n_in,
                              void* d_out, int out_size) {
    const float* x       = (const float*)d_in[0];
    const float* signs   = (const float*)d_in[1];
    const float* ps      = (const float*)d_in[2];
    const float* routing = (const float*)d_in[3];
    for (int i = 0; i < n_in; i++) {
        if (in_sizes[i] == M_TOT * K_TOT)      x       = (const float*)d_in[i];
        else if (in_sizes[i] == N_TOT * K_TOT) signs   = (const float*)d_in[i];
        else if (in_sizes[i] == NPROF * GTOT)  ps      = (const float*)d_in[i];
        else if (in_sizes[i] == NPROF)         routing = (const float*)d_in[i];
    }
    float* out = (float*)d_out;

    cudaFuncSetAttribute(gemm_kernel, cudaFuncAttributeMaxDynamicSharedMemorySize, SMEM_TOTAL);

    prep_x_kernel<<<M_TOT * K_TOT / 4 / 4 / 256, 256>>>(x);
    prep_w_kernel<<<N_TOT, 256>>>(signs, ps, routing);
    gemm_kernel<<<(M_TOT / BM) * (N_TOT / BN), THREADS, SMEM_TOTAL>>>(out);
}

// round 4
// speedup vs baseline: 1.0615x; 1.0615x over previous
#include <cuda_runtime.h>
#include <cuda_fp16.h>
#include <cstdint>

// ============================================================================
// Problem constants
// ============================================================================
static constexpr int M_TOT = 8192;
static constexpr int N_TOT = 4096;
static constexpr int K_TOT = 4096;
static constexpr int GROUP = 128;
static constexpr int NPROF = 8;
static constexpr int GTOT  = N_TOT * K_TOT / GROUP;

// GEMM tiling: CTA 128x128x64, warp tile 32x64 (8 warps: 4M x 2N), occupancy 2
static constexpr int BM = 128;
static constexpr int BN = 128;
static constexpr int BK = 64;
static constexpr int KITERS = K_TOT / BK;     // 64
static constexpr int STAGES = 3;

static constexpr int A_BYTES = BM * 128;      // 16384
static constexpr int B_BYTES = BN * 128;      // 16384
static constexpr int STAGE_BYTES = A_BYTES + B_BYTES;     // 32768
static constexpr int SMEM_TOTAL  = STAGES * STAGE_BYTES;  // 98304 -> 2 CTAs/SM

static constexpr int THREADS = 256;           // 8 warps

// ============================================================================
// Scratch device globals
// ============================================================================
__device__ __align__(1024) __half g_A[(size_t)M_TOT * K_TOT];  // 64 MB
__device__ __align__(1024) __half g_B[(size_t)N_TOT * K_TOT];  // 32 MB

// ============================================================================
// PTX helpers (baseline features only — harness assembles at plain sm_103)
// ============================================================================
__device__ __forceinline__ uint32_t smem_u32(const void* p) {
    uint32_t a;
    asm("{ .reg .u64 t; cvta.to.shared.u64 t, %1; cvt.u32.u64 %0, t; }" : "=r"(a) : "l"(p));
    return a;
}
__device__ __forceinline__ void cp_async16(uint32_t dst, const void* src) {
    asm volatile("cp.async.cg.shared.global [%0], [%1], 16;" :: "r"(dst), "l"(src) : "memory");
}
__device__ __forceinline__ void cp_commit() {
    asm volatile("cp.async.commit_group;" ::: "memory");
}
template <int N>
__device__ __forceinline__ void cp_wait() {
    asm volatile("cp.async.wait_group %0;" :: "n"(N) : "memory");
}
#define LDSM_X4(r0, r1, r2, r3, addr)                                              \
    asm volatile("ldmatrix.sync.aligned.m8n8.x4.shared.b16 {%0,%1,%2,%3}, [%4];"   \
                 : "=r"(r0), "=r"(r1), "=r"(r2), "=r"(r3) : "r"(addr))

__device__ __forceinline__ void mma16816(float* c, const uint32_t* a, uint32_t b0, uint32_t b1) {
    asm volatile(
        "mma.sync.aligned.m16n8k16.row.col.f32.f16.f16.f32 "
        "{%0,%1,%2,%3}, {%4,%5,%6,%7}, {%8,%9}, {%0,%1,%2,%3};"
        : "+f"(c[0]), "+f"(c[1]), "+f"(c[2]), "+f"(c[3])
        : "r"(a[0]), "r"(a[1]), "r"(a[2]), "r"(a[3]), "r"(b0), "r"(b1));
}

// ============================================================================
// Prep 1: x fp32 -> fp16 row-major [M, K]
// ============================================================================
__global__ void __launch_bounds__(256) prep_x_kernel(const float* __restrict__ x) {
    const int idx0 = blockIdx.x * 256 + threadIdx.x;
    const float4* __restrict__ x4 = (const float4*)x;
    uint2* __restrict__ dst = (uint2*)g_A;
#pragma unroll
    for (int i = 0; i < 4; i++) {
        const int id = idx0 + i * (M_TOT * K_TOT / 4 / 4);
        float4 v = x4[id];
        __half2 h0 = __floats2half2_rn(v.x, v.y);
        __half2 h1 = __floats2half2_rn(v.z, v.w);
        uint2 u;
        u.x = *reinterpret_cast<uint32_t*>(&h0);
        u.y = *reinterpret_cast<uint32_t*>(&h1);
        dst[id] = u;
    }
}

// ============================================================================
// Prep 2: W[n][k] = sign[n][k] * blended_scale[n*32 + k/128], fp16
// ============================================================================
__global__ void __launch_bounds__(256) prep_w_kernel(const float* __restrict__ signs,
                                                     const float* __restrict__ ps,
                                                     const float* __restrict__ routing) {
    __shared__ float s_rt[NPROF];
    __shared__ float s_sc[K_TOT / GROUP];
    const int n = blockIdx.x;
    const int tid = threadIdx.x;
    if (tid < NPROF) s_rt[tid] = routing[tid];
    __syncthreads();
    if (tid < K_TOT / GROUP) {
        const int g = n * (K_TOT / GROUP) + tid;
        float s = 0.f;
#pragma unroll
        for (int p = 0; p < NPROF; p++) s += s_rt[p] * ps[(size_t)p * GTOT + g];
        s_sc[tid] = s;
    }
    __syncthreads();

    const float sc = s_sc[tid >> 3];
    const float4* __restrict__ sr = (const float4*)(signs + (size_t)n * K_TOT) + tid * 4;
    uint2* __restrict__ dst = (uint2*)(g_B + (size_t)n * K_TOT + tid * 16);
#pragma unroll
    for (int j = 0; j < 4; j++) {
        float4 v = sr[j];
        __half2 h0 = __floats2half2_rn(v.x * sc, v.y * sc);
        __half2 h1 = __floats2half2_rn(v.z * sc, v.w * sc);
        uint2 u;
        u.x = *reinterpret_cast<uint32_t*>(&h0);
        u.y = *reinterpret_cast<uint32_t*>(&h1);
        dst[j] = u;
    }
}

// ============================================================================
// GEMM: out[M,N] = Ah @ Bh^T, fp32 accum. CTA 128x128x64, warp 32x64, occ 2.
// ============================================================================
__global__ void __launch_bounds__(THREADS, 2) gemm_kernel(float* __restrict__ out) {
    extern __shared__ __align__(1024) unsigned char smem[];
    const uint32_t sb = smem_u32(smem);
    const int tid = threadIdx.x;
    const int wid = tid >> 5;
    const int lid = tid & 31;

    const int mBlk = blockIdx.x >> 5;       // 0..63
    const int nBlk = blockIdx.x & 31;       // 0..31
    const int mBase = mBlk * BM;
    const int nBase = nBlk * BN;

    const int wm = wid >> 1;                // 0..3
    const int wn = wid & 1;                 // 0..1
    const int wmBase = wm * 32;
    const int wnBase = wn * 64;

    // ---- per-lane ldmatrix address components ----
    int rowOffA[2], xorA[2];
    const int hiA = (lid >> 4) & 1;
#pragma unroll
    for (int mi = 0; mi < 2; mi++) {
        int r = wmBase + mi * 16 + ((lid >> 3) & 1) * 8 + (lid & 7);
        rowOffA[mi] = r * 128;
        xorA[mi] = r & 7;
    }
    int rowOffB[4], xorB[4];
    const int hiB = (lid >> 3) & 1;
#pragma unroll
    for (int g = 0; g < 4; g++) {
        int r = wnBase + g * 16 + ((lid >> 4) & 1) * 8 + (lid & 7);
        rowOffB[g] = r * 128;
        xorB[g] = r & 7;
    }

    float acc[2][8][4];
#pragma unroll
    for (int mi = 0; mi < 2; mi++)
#pragma unroll
        for (int ni = 0; ni < 8; ni++)
#pragma unroll
            for (int j = 0; j < 4; j++) acc[mi][ni][j] = 0.f;

    const __half* __restrict__ gApan = g_A + (size_t)mBase * K_TOT;
    const __half* __restrict__ gBpan = g_B + (size_t)nBase * K_TOT;

    // ---- stage loader: A 1024 + B 1024 16B chunks over 256 threads ----
    auto load_stage = [&](int kt, int st) {
        const uint32_t stA = sb + st * STAGE_BYTES;
        const uint32_t stB = stA + A_BYTES;
        const __half* srcA = gApan + kt * BK;
        const __half* srcB = gBpan + kt * BK;
#pragma unroll
        for (int i = 0; i < 4; i++) {           // A: 128 rows x 8 chunks
            int t = tid + i * THREADS;
            int row = t >> 3, c16 = t & 7;
            uint32_t dst = stA + row * 128 + ((c16 ^ (row & 7)) << 4);
            cp_async16(dst, srcA + (size_t)row * K_TOT + c16 * 8);
        }
#pragma unroll
        for (int i = 0; i < 4; i++) {           // B: 128 rows x 8 chunks
            int t = tid + i * THREADS;
            int row = t >> 3, c16 = t & 7;
            uint32_t dst = stB + row * 128 + ((c16 ^ (row & 7)) << 4);
            cp_async16(dst, srcB + (size_t)row * K_TOT + c16 * 8);
        }
        cp_commit();
    };

    // ---- prologue: fill stages 0..STAGES-2 ----
#pragma unroll
    for (int s = 0; s < STAGES - 1; s++) load_stage(s, s);

    // ---- main loop (rolling stage counters; STAGES=3, not a power of 2) ----
    int stC = 0;                   // compute stage
    int stL = STAGES - 1;          // load stage
    for (int kt = 0; kt < KITERS; kt++) {
        cp_wait<STAGES - 2>();
        __syncthreads();

        if (kt + STAGES - 1 < KITERS) {
            load_stage(kt + STAGES - 1, stL);
            if (++stL == STAGES) stL = 0;
        }

        const uint32_t stA = sb + stC * STAGE_BYTES;
        const uint32_t stB = stA + A_BYTES;
        if (++stC == STAGES) stC = 0;

#pragma unroll
        for (int ks = 0; ks < 4; ks++) {
            uint32_t a[2][4];
#pragma unroll
            for (int mi = 0; mi < 2; mi++) {
                uint32_t addr = stA + rowOffA[mi] + (((ks * 2 + hiA) ^ xorA[mi]) << 4);
                LDSM_X4(a[mi][0], a[mi][1], a[mi][2], a[mi][3], addr);
            }
            uint32_t b[4][4];
#pragma unroll
            for (int g = 0; g < 4; g++) {
                uint32_t addr = stB + rowOffB[g] + (((ks * 2 + hiB) ^ xorB[g]) << 4);
                LDSM_X4(b[g][0], b[g][1], b[g][2], b[g][3], addr);
            }
#pragma unroll
            for (int mi = 0; mi < 2; mi++)
#pragma unroll
                for (int ni = 0; ni < 8; ni++) {
                    const int g = ni >> 1, sel = (ni & 1) * 2;
                    mma16816(acc[mi][ni], a[mi], b[g][sel], b[g][sel + 1]);
                }
        }
    }

    // ---- epilogue: direct fp32 stores ----
    const int gr = lid >> 2, tig = lid & 3;
#pragma unroll
    for (int mi = 0; mi < 2; mi++) {
        const int row0 = mBase + wmBase + mi * 16 + gr;
#pragma unroll
        for (int ni = 0; ni < 8; ni++) {
            const int col = nBase + wnBase + ni * 8 + tig * 2;
            float2* p0 = reinterpret_cast<float2*>(out + (size_t)row0 * N_TOT + col);
            float2* p1 = reinterpret_cast<float2*>(out + (size_t)(row0 + 8) * N_TOT + col);
            *p0 = make_float2(acc[mi][ni][0], acc[mi][ni][1]);
            *p1 = make_float2(acc[mi][ni][2], acc[mi][ni][3]);
        }
    }
}

// ============================================================================
// Launch
// ============================================================================
extern "C" void kernel_launch(void* const* d_in, const int* in_sizes, int n_in,
                              void* d_out, int out_size) {
    const float* x       = (const float*)d_in[0];
    const float* signs   = (const float*)d_in[1];
    const float* ps      = (const float*)d_in[2];
    const float* routing = (const float*)d_in[3];
    for (int i = 0; i < n_in; i++) {
        if (in_sizes[i] == M_TOT * K_TOT)      x       = (const float*)d_in[i];
        else if (in_sizes[i] == N_TOT * K_TOT) signs   = (const float*)d_in[i];
        else if (in_sizes[i] == NPROF * GTOT)  ps      = (const float*)d_in[i];
        else if (in_sizes[i] == NPROF)         routing = (const float*)d_in[i];
    }
    float* out = (float*)d_out;

    cudaFuncSetAttribute(gemm_kernel, cudaFuncAttributeMaxDynamicSharedMemorySize, SMEM_TOTAL);

    prep_x_kernel<<<M_TOT * K_TOT / 4 / 4 / 256, 256>>>(x);
    prep_w_kernel<<<N_TOT, 256>>>(signs, ps, routing);
    gemm_kernel<<<(M_TOT / BM) * (N_TOT / BN), THREADS, SMEM_TOTAL>>>(out);
}